// round 2
// baseline (speedup 1.0000x reference)
#include <cuda_runtime.h>
#include <cstdint>
#include <cstddef>

// Problem constants (fixed by the dataset)
#define NJ   100000
#define NS   20000
#define NM   10000
#define NR   5000
#define EE   250000
#define DIN  128
#define OUTD 256
#define NTOT 65000      // concatenated src rows: 20000+20000+10000+10000+5000
#define NCOMB 320       // W_res(256) + Wd(20) + pad(44) -> multiple of 64

// ---------------- device scratch (static; no runtime allocation) ----------------
__device__ float g_hs[(size_t)NTOT * 256];        // per-relation hs = x_src @ W_r
__device__ float g_as[NTOT * 4];                  // a_src per node per head
__device__ float g_resad[(size_t)NJ * NCOMB];     // [0:256)=x_job@W_res, [256:276)=a_dst per (rel,head)
__device__ float g_wcomb[DIN * NCOMB];            // combined [W_res | Wd | 0]
__device__ float g_bsum[OUTD];                    // sum of relation biases
__device__ int   g_off[5 * (NJ + 1)];             // CSR offsets per relation
__device__ int   g_cur[5 * NJ];                   // fill cursors
__device__ int   g_esrc[5 * EE];                  // CSR: src node per slot

__constant__ int c_hsb[5] = {0, 20000, 40000, 50000, 60000};

__device__ __forceinline__ float lrelu(float v) { return v > 0.f ? v : 0.2f * v; }

// ---------------- prep: build combined W matrix [W_res | Wd(r,h) | pad] ----------------
__global__ void k_prep_w(const float* __restrict__ W_res, const float* __restrict__ Ws,
                         const float* __restrict__ att_dst) {
    int k = blockIdx.x;           // 0..127
    int col = threadIdx.x;        // 0..319
    float v = 0.f;
    if (col < 256) {
        v = W_res[k * 256 + col];
    } else if (col < 276) {
        int rr = (col - 256) >> 2, hh = (col - 256) & 3;
        const float* w = Ws + ((size_t)rr * DIN + k) * 256 + hh * 64;
        const float* a = att_dst + rr * 256 + hh * 64;
        float s = 0.f;
        #pragma unroll
        for (int c = 0; c < 64; c++) s += w[c] * a[c];
        v = s;
    }
    g_wcomb[k * NCOMB + col] = v;
}

__global__ void k_bsum(const float* __restrict__ biases) {
    int t = threadIdx.x;
    float s = 0.f;
    #pragma unroll
    for (int r = 0; r < 5; r++) s += biases[r * 256 + t];
    g_bsum[t] = s;
}

__global__ void k_zero() {
    int n = 5 * (NJ + 1);
    for (int i = blockIdx.x * blockDim.x + threadIdx.x; i < n; i += gridDim.x * blockDim.x)
        g_off[i] = 0;
}

// ---------------- fp32 SGEMM: C[M,N] = A[M,128] @ B[128,N]; BM=128 BN=64 BK=16 ----------------
// mode==0 -> B=Bin,     C = g_hs + coff
// mode==1 -> B=g_wcomb, C = g_resad + coff   (g_wcomb MUST be resolved device-side!)
__global__ __launch_bounds__(256) void k_gemm(const float* __restrict__ A, int M,
                                              const float* __restrict__ Bin, int N,
                                              int mode, int coff) {
    __shared__ float As[16][132];
    __shared__ float Bs[16][64];
    const float* __restrict__ B = (mode == 1) ? (const float*)g_wcomb : Bin;
    float* __restrict__ C = (mode == 1 ? g_resad : g_hs) + coff;
    int tid = threadIdx.x;
    int bm0 = blockIdx.y * 128, bn0 = blockIdx.x * 64;
    int tx = tid & 15, ty = tid >> 4;
    float acc[8][4];
    #pragma unroll
    for (int i = 0; i < 8; i++)
        #pragma unroll
        for (int jj = 0; jj < 4; jj++) acc[i][jj] = 0.f;

    for (int k0 = 0; k0 < DIN; k0 += 16) {
        #pragma unroll
        for (int l = 0; l < 2; l++) {
            int f = tid + l * 256;
            int row = f >> 2, c4 = f & 3;
            int gr = bm0 + row;
            float4 av = make_float4(0.f, 0.f, 0.f, 0.f);
            if (gr < M) av = *(const float4*)(A + (size_t)gr * DIN + k0 + c4 * 4);
            As[c4 * 4 + 0][row] = av.x;
            As[c4 * 4 + 1][row] = av.y;
            As[c4 * 4 + 2][row] = av.z;
            As[c4 * 4 + 3][row] = av.w;
        }
        {
            int row = tid >> 4, cc = tid & 15;
            *(float4*)&Bs[row][cc * 4] = *(const float4*)(B + (size_t)(k0 + row) * N + bn0 + cc * 4);
        }
        __syncthreads();
        #pragma unroll
        for (int kk = 0; kk < 16; kk++) {
            float ra[8], rb[4];
            *(float4*)(ra)     = *(const float4*)&As[kk][ty * 8];
            *(float4*)(ra + 4) = *(const float4*)&As[kk][ty * 8 + 4];
            *(float4*)(rb)     = *(const float4*)&Bs[kk][tx * 4];
            #pragma unroll
            for (int i = 0; i < 8; i++)
                #pragma unroll
                for (int jj = 0; jj < 4; jj++)
                    acc[i][jj] = fmaf(ra[i], rb[jj], acc[i][jj]);
        }
        __syncthreads();
    }
    #pragma unroll
    for (int i = 0; i < 8; i++) {
        int gr = bm0 + ty * 8 + i;
        if (gr < M) *(float4*)(C + (size_t)gr * N + bn0 + tx * 4) = *(float4*)(acc[i]);
    }
}

// ---------------- a_src reduction: one warp per node ----------------
__global__ void k_as(const float* __restrict__ att, int base, int M) {
    int node = blockIdx.x * 8 + (threadIdx.x >> 5);
    if (node >= M) return;
    int lane = threadIdx.x & 31;
    const float* hrow = g_hs + (size_t)(base + node) * 256 + lane * 8;
    const float* a = att + lane * 8;
    float4 h0 = *(const float4*)hrow;
    float4 h1 = *(const float4*)(hrow + 4);
    float4 a0 = *(const float4*)a;
    float4 a1 = *(const float4*)(a + 4);
    float p = h0.x * a0.x + h0.y * a0.y + h0.z * a0.z + h0.w * a0.w +
              h1.x * a1.x + h1.y * a1.y + h1.z * a1.z + h1.w * a1.w;
    p += __shfl_xor_sync(0xffffffffu, p, 4);
    p += __shfl_xor_sync(0xffffffffu, p, 2);
    p += __shfl_xor_sync(0xffffffffu, p, 1);
    if ((lane & 7) == 0) g_as[(size_t)(base + node) * 4 + (lane >> 3)] = p;
}

// ---------------- CSR build ----------------
__global__ void k_hist(const int* __restrict__ dst, int r) {
    int* cnt = g_off + r * (NJ + 1);
    for (int i = blockIdx.x * blockDim.x + threadIdx.x; i < EE; i += gridDim.x * blockDim.x)
        atomicAdd(&cnt[dst[i]], 1);
}

__global__ __launch_bounds__(1024) void k_scan() {
    __shared__ int sd[1024];
    __shared__ int s_carry;
    int r = blockIdx.x;
    int* cnt = g_off + r * (NJ + 1);
    int* cur = g_cur + r * NJ;
    int tid = threadIdx.x;
    if (tid == 0) s_carry = 0;
    __syncthreads();
    for (int base = 0; base < NJ; base += 1024) {
        int i = base + tid;
        int v = (i < NJ) ? cnt[i] : 0;
        sd[tid] = v;
        __syncthreads();
        for (int o = 1; o < 1024; o <<= 1) {
            int t = (tid >= o) ? sd[tid - o] : 0;
            __syncthreads();
            sd[tid] += t;
            __syncthreads();
        }
        int excl = sd[tid] - v;
        int carry = s_carry;
        if (i < NJ) { int off = carry + excl; cnt[i] = off; cur[i] = off; }
        int tot = sd[1023];
        __syncthreads();
        if (tid == 0) s_carry = carry + tot;
        __syncthreads();
    }
    if (tid == 0) cnt[NJ] = s_carry;
}

__global__ void k_fill(const int* __restrict__ src, const int* __restrict__ dst, int r) {
    int* cur = g_cur + r * NJ;
    int* es = g_esrc + r * EE;
    for (int i = blockIdx.x * blockDim.x + threadIdx.x; i < EE; i += gridDim.x * blockDim.x) {
        int d = dst[i];
        int slot = atomicAdd(&cur[d], 1);
        es[slot] = src[i];
    }
}

// ---------------- fused main: per-dst softmax gather + residual + ReLU + LayerNorm ----------------
#define CH 64
__global__ __launch_bounds__(256) void k_main(const float* __restrict__ gamma,
                                              const float* __restrict__ beta,
                                              float* __restrict__ out) {
    __shared__ float4 s_e[CH];
    __shared__ float4 s_w[CH];
    __shared__ int    s_src[CH];
    __shared__ float  s_m[4], s_den[4], s_scale[4];
    __shared__ float  s_r1[8], s_r2[8];

    int j = blockIdx.x;
    int tid = threadIdx.x;
    int h = tid >> 6;
    const float* row = g_resad + (size_t)j * NCOMB;
    float acc = row[tid] + g_bsum[tid];

    #pragma unroll
    for (int r = 0; r < 5; r++) {
        int beg = g_off[r * (NJ + 1) + j];
        int end = g_off[r * (NJ + 1) + j + 1];
        if (beg == end) continue;              // uniform per block
        __syncthreads();                       // protect s_* reuse across relations
        if (tid < 4) { s_m[tid] = -1e30f; s_den[tid] = 0.f; }
        float tmp = 0.f;
        int hsb = c_hsb[r];
        __syncthreads();

        for (int pos = beg; pos < end; pos += CH) {
            int cnt = min(CH, end - pos);
            if (tid < cnt) {
                int s = g_esrc[r * EE + pos + tid];
                s_src[tid] = s;
                float4 a4 = *(const float4*)(g_as + (size_t)(hsb + s) * 4);
                float4 d4 = *(const float4*)(row + 256 + r * 4);
                float4 e4;
                e4.x = lrelu(a4.x + d4.x);
                e4.y = lrelu(a4.y + d4.y);
                e4.z = lrelu(a4.z + d4.z);
                e4.w = lrelu(a4.w + d4.w);
                s_e[tid] = e4;
            }
            __syncthreads();
            if (tid < 4) {   // per-head streaming softmax bookkeeping
                float m = s_m[tid], den = s_den[tid];
                float cm = -1e30f;
                for (int k = 0; k < cnt; k++) cm = fmaxf(cm, ((const float*)&s_e[k])[tid]);
                float nm = fmaxf(m, cm);
                float sc = __expf(m - nm);
                den *= sc;
                for (int k = 0; k < cnt; k++) {
                    float ex = __expf(((const float*)&s_e[k])[tid] - nm);
                    den += ex;
                    ((float*)&s_w[k])[tid] = ex;
                }
                s_m[tid] = nm; s_den[tid] = den; s_scale[tid] = sc;
            }
            __syncthreads();
            tmp *= s_scale[h];
            const float* hsr = g_hs + (size_t)hsb * 256 + tid;
            for (int k = 0; k < cnt; k++) {
                float w = ((const float*)&s_w[k])[h];
                tmp = fmaf(w, hsr[(size_t)s_src[k] * 256], tmp);
            }
            __syncthreads();
        }
        acc += tmp / (s_den[h] + 1e-16f);
    }

    // ReLU + LayerNorm over the 256 channels of this block
    float v = fmaxf(acc, 0.f);
    float s1 = v, s2 = v * v;
    #pragma unroll
    for (int o = 16; o > 0; o >>= 1) {
        s1 += __shfl_xor_sync(0xffffffffu, s1, o);
        s2 += __shfl_xor_sync(0xffffffffu, s2, o);
    }
    int w = tid >> 5;
    if ((tid & 31) == 0) { s_r1[w] = s1; s_r2[w] = s2; }
    __syncthreads();
    if (tid < 32) {
        float a = (tid < 8) ? s_r1[tid] : 0.f;
        float b = (tid < 8) ? s_r2[tid] : 0.f;
        #pragma unroll
        for (int o = 4; o > 0; o >>= 1) {
            a += __shfl_xor_sync(0xffffffffu, a, o);
            b += __shfl_xor_sync(0xffffffffu, b, o);
        }
        if (tid == 0) { s_r1[0] = a; s_r2[0] = b; }
    }
    __syncthreads();
    float mu = s_r1[0] * (1.f / 256.f);
    float var = s_r2[0] * (1.f / 256.f) - mu * mu;
    out[(size_t)j * 256 + tid] = (v - mu) * rsqrtf(var + 1e-5f) * gamma[tid] + beta[tid];
}

// ---------------- launch ----------------
extern "C" void kernel_launch(void* const* d_in, const int* in_sizes, int n_in,
                              void* d_out, int out_size) {
    const float* x_job     = (const float*)d_in[0];
    const float* x_station = (const float*)d_in[1];
    const float* x_machine = (const float*)d_in[2];
    const float* x_robot   = (const float*)d_in[3];
    const int* srcp[5] = {(const int*)d_in[4], (const int*)d_in[6], (const int*)d_in[8],
                          (const int*)d_in[10], (const int*)d_in[12]};
    const int* dstp[5] = {(const int*)d_in[5], (const int*)d_in[7], (const int*)d_in[9],
                          (const int*)d_in[11], (const int*)d_in[13]};
    const float* Ws      = (const float*)d_in[14];
    const float* att_src = (const float*)d_in[15];
    const float* att_dst = (const float*)d_in[16];
    const float* biases  = (const float*)d_in[17];
    const float* W_res   = (const float*)d_in[18];
    const float* gamma   = (const float*)d_in[19];
    const float* beta    = (const float*)d_in[20];
    float* out = (float*)d_out;

    (void)in_sizes; (void)n_in; (void)out_size;

    const float* xs[5] = {x_station, x_station, x_machine, x_machine, x_robot};
    const int Ms[5]  = {NS, NS, NM, NM, NR};
    const int hb[5]  = {0, 20000, 40000, 50000, 60000};

    // prep
    k_prep_w<<<DIN, NCOMB>>>(W_res, Ws, att_dst);
    k_bsum<<<1, 256>>>(biases);
    k_zero<<<256, 256>>>();

    // GEMMs: hs per relation
    for (int r = 0; r < 5; r++) {
        dim3 grid(256 / 64, (Ms[r] + 127) / 128);
        k_gemm<<<grid, 256>>>(xs[r], Ms[r], Ws + (size_t)r * DIN * 256, 256, 0, hb[r] * 256);
    }
    // combined residual + a_dst GEMM (B = g_wcomb selected DEVICE-side via mode==1;
    // passing the __device__ symbol from host code silently reads the host shadow
    // address on GB300 ATS — that was the round-1 bug)
    {
        dim3 grid(NCOMB / 64, (NJ + 127) / 128);
        k_gemm<<<grid, 256>>>(x_job, NJ, (const float*)nullptr, NCOMB, 1, 0);
    }
    // a_src reductions
    for (int r = 0; r < 5; r++) {
        int blocks = (Ms[r] + 7) / 8;
        k_as<<<blocks, 256>>>(att_src + r * 256, hb[r], Ms[r]);
    }
    // CSR build
    for (int r = 0; r < 5; r++) k_hist<<<256, 256>>>(dstp[r], r);
    k_scan<<<5, 1024>>>();
    for (int r = 0; r < 5; r++) k_fill<<<256, 256>>>(srcp[r], dstp[r], r);

    // fused gather + residual + relu + layernorm
    k_main<<<NJ, 256>>>(gamma, beta, out);
}

// round 3
// speedup vs baseline: 1.2879x; 1.2879x over previous
#include <cuda_runtime.h>
#include <cstdint>
#include <cstddef>

// Problem constants (fixed by the dataset)
#define NJ   100000
#define NS   20000
#define NM   10000
#define NR   5000
#define EE   250000
#define DIN  128
#define OUTD 256
#define NTOT 65000      // concatenated src rows: 20000+20000+10000+10000+5000
#define NCOMB 320       // W_res(256) + Wd(20) + pad(44) -> multiple of 64

typedef unsigned long long ull;

// ---------------- device scratch (static; no runtime allocation) ----------------
__device__ __align__(16) float g_hs[(size_t)NTOT * 256];   // per-relation hs = x_src @ W_r
__device__ __align__(16) float g_as[NTOT * 4];             // a_src per node per head
__device__ __align__(16) float g_resad[(size_t)NJ * NCOMB];// [0:256)=x_job@W_res, [256:276)=a_dst
__device__ float g_wcomb[DIN * NCOMB];                     // combined [W_res | Wd | 0]
__device__ float g_bsum[OUTD];                             // sum of relation biases
__device__ int   g_off[5 * (NJ + 1)];                      // CSR offsets per relation
__device__ int   g_cur[5 * NJ];                            // fill cursors
__device__ int   g_esrc[5 * EE];                           // CSR: src node per slot
__device__ float4 g_walpha[5 * EE];                        // normalized attention per edge (4 heads)
__device__ int   g_tile[5 * 128];                          // scan tile sums

__constant__ int c_hsb[5] = {0, 20000, 40000, 50000, 60000};

__device__ __forceinline__ float lrelu(float v) { return v > 0.f ? v : 0.2f * v; }

__device__ __forceinline__ void fma2(ull& d, ull a, ull b) {
    asm("fma.rn.f32x2 %0, %1, %2, %0;" : "+l"(d) : "l"(a), "l"(b));
}
__device__ __forceinline__ void unpk(float& lo, float& hi, ull v) {
    asm("mov.b64 {%0,%1}, %2;" : "=f"(lo), "=f"(hi) : "l"(v));
}

// ---------------- prep: build combined W matrix [W_res | Wd(r,h) | pad] ----------------
__global__ void k_prep_w(const float* __restrict__ W_res, const float* __restrict__ Ws,
                         const float* __restrict__ att_dst) {
    int k = blockIdx.x;           // 0..127
    int col = threadIdx.x;        // 0..319
    float v = 0.f;
    if (col < 256) {
        v = W_res[k * 256 + col];
    } else if (col < 276) {
        int rr = (col - 256) >> 2, hh = (col - 256) & 3;
        const float* w = Ws + ((size_t)rr * DIN + k) * 256 + hh * 64;
        const float* a = att_dst + rr * 256 + hh * 64;
        float s = 0.f;
        #pragma unroll
        for (int c = 0; c < 64; c++) s += w[c] * a[c];
        v = s;
    }
    g_wcomb[k * NCOMB + col] = v;
}

__global__ void k_bsum(const float* __restrict__ biases) {
    int t = threadIdx.x;
    float s = 0.f;
    #pragma unroll
    for (int r = 0; r < 5; r++) s += biases[r * 256 + t];
    g_bsum[t] = s;
}

__global__ void k_zero() {
    int n = 5 * (NJ + 1);
    for (int i = blockIdx.x * blockDim.x + threadIdx.x; i < n; i += gridDim.x * blockDim.x)
        g_off[i] = 0;
}

// ---------------- fp32x2 SGEMM: C[M,N] = A[M,128] @ B[128,N]; BM=128 BN=64 BK=16 ----------------
// mode==0 -> B=Bin,     C = g_hs + coff
// mode==1 -> B=g_wcomb, C = g_resad + coff   (g_wcomb resolved device-side!)
__global__ __launch_bounds__(256) void k_gemm(const float* __restrict__ A, int M,
                                              const float* __restrict__ Bin, int N,
                                              int mode, int coff) {
    __shared__ float As[16][132];     // [k][m], 528B row stride (16B aligned)
    __shared__ float Bs2[16][128];    // duplicated pairs: [k][2c]=[k][2c+1]=B[k][bn0+c]
    const float* __restrict__ B = (mode == 1) ? (const float*)g_wcomb : Bin;
    float* __restrict__ C = (mode == 1 ? g_resad : g_hs) + coff;
    int tid = threadIdx.x;
    int bm0 = blockIdx.y * 128, bn0 = blockIdx.x * 64;
    int tx = tid & 15, ty = tid >> 4;

    ull acc2[4][4];   // [row-pair][col]: rows (ty*8+2i2, +1), cols bn0+tx*4+j
    #pragma unroll
    for (int i = 0; i < 4; i++)
        #pragma unroll
        for (int j = 0; j < 4; j++) acc2[i][j] = 0ull;

    for (int k0 = 0; k0 < DIN; k0 += 16) {
        #pragma unroll
        for (int l = 0; l < 2; l++) {
            int f = tid + l * 256;
            int row = f >> 2, c4 = f & 3;
            int gr = bm0 + row;
            float4 av = make_float4(0.f, 0.f, 0.f, 0.f);
            if (gr < M) av = *(const float4*)(A + (size_t)gr * DIN + k0 + c4 * 4);
            As[c4 * 4 + 0][row] = av.x;
            As[c4 * 4 + 1][row] = av.y;
            As[c4 * 4 + 2][row] = av.z;
            As[c4 * 4 + 3][row] = av.w;
        }
        {
            int row = tid >> 4, cc = tid & 15;
            float4 b = *(const float4*)(B + (size_t)(k0 + row) * N + bn0 + cc * 4);
            float2* p = (float2*)&Bs2[row][cc * 8];
            p[0] = make_float2(b.x, b.x);
            p[1] = make_float2(b.y, b.y);
            p[2] = make_float2(b.z, b.z);
            p[3] = make_float2(b.w, b.w);
        }
        __syncthreads();
        #pragma unroll
        for (int kk = 0; kk < 16; kk++) {
            // A row pairs come packed directly from consecutive smem floats
            ulonglong2 a01 = *(const ulonglong2*)&As[kk][ty * 8];
            ulonglong2 a23 = *(const ulonglong2*)&As[kk][ty * 8 + 4];
            ulonglong2 b01 = *(const ulonglong2*)&Bs2[kk][tx * 8];
            ulonglong2 b23 = *(const ulonglong2*)&Bs2[kk][tx * 8 + 4];
            ull ap[4] = {a01.x, a01.y, a23.x, a23.y};
            ull bp[4] = {b01.x, b01.y, b23.x, b23.y};
            #pragma unroll
            for (int i = 0; i < 4; i++)
                #pragma unroll
                for (int j = 0; j < 4; j++)
                    fma2(acc2[i][j], ap[i], bp[j]);
        }
        __syncthreads();
    }
    #pragma unroll
    for (int i2 = 0; i2 < 4; i2++) {
        float lo[4], hi[4];
        #pragma unroll
        for (int j = 0; j < 4; j++) unpk(lo[j], hi[j], acc2[i2][j]);
        int gr0 = bm0 + ty * 8 + 2 * i2;
        if (gr0 < M)
            *(float4*)(C + (size_t)gr0 * N + bn0 + tx * 4) = make_float4(lo[0], lo[1], lo[2], lo[3]);
        if (gr0 + 1 < M)
            *(float4*)(C + (size_t)(gr0 + 1) * N + bn0 + tx * 4) = make_float4(hi[0], hi[1], hi[2], hi[3]);
    }
}

// ---------------- a_src reduction: one warp per node ----------------
__global__ void k_as(const float* __restrict__ att, int base, int M) {
    int node = blockIdx.x * 8 + (threadIdx.x >> 5);
    if (node >= M) return;
    int lane = threadIdx.x & 31;
    const float* hrow = g_hs + (size_t)(base + node) * 256 + lane * 8;
    const float* a = att + lane * 8;
    float4 h0 = *(const float4*)hrow;
    float4 h1 = *(const float4*)(hrow + 4);
    float4 a0 = *(const float4*)a;
    float4 a1 = *(const float4*)(a + 4);
    float p = h0.x * a0.x + h0.y * a0.y + h0.z * a0.z + h0.w * a0.w +
              h1.x * a1.x + h1.y * a1.y + h1.z * a1.z + h1.w * a1.w;
    p += __shfl_xor_sync(0xffffffffu, p, 4);
    p += __shfl_xor_sync(0xffffffffu, p, 2);
    p += __shfl_xor_sync(0xffffffffu, p, 1);
    if ((lane & 7) == 0) g_as[(size_t)(base + node) * 4 + (lane >> 3)] = p;
}

// ---------------- CSR build ----------------
__global__ void k_hist5(const int* __restrict__ d0, const int* __restrict__ d1,
                        const int* __restrict__ d2, const int* __restrict__ d3,
                        const int* __restrict__ d4) {
    for (int i = blockIdx.x * blockDim.x + threadIdx.x; i < EE; i += gridDim.x * blockDim.x) {
        atomicAdd(&g_off[0 * (NJ + 1) + d0[i]], 1);
        atomicAdd(&g_off[1 * (NJ + 1) + d1[i]], 1);
        atomicAdd(&g_off[2 * (NJ + 1) + d2[i]], 1);
        atomicAdd(&g_off[3 * (NJ + 1) + d3[i]], 1);
        atomicAdd(&g_off[4 * (NJ + 1) + d4[i]], 1);
    }
}

// tile scan: 1024 counts per block, 512 threads x 2 elems
__global__ __launch_bounds__(512) void k_scan1() {
    __shared__ int sd[512];
    int r = blockIdx.y, tile = blockIdx.x, tid = threadIdx.x;
    int* cnt = g_off + r * (NJ + 1);
    int i0 = tile * 1024 + 2 * tid;
    int v0 = (i0 < NJ) ? cnt[i0] : 0;
    int v1 = (i0 + 1 < NJ) ? cnt[i0 + 1] : 0;
    int sum = v0 + v1;
    sd[tid] = sum;
    __syncthreads();
    #pragma unroll
    for (int o = 1; o < 512; o <<= 1) {
        int t = (tid >= o) ? sd[tid - o] : 0;
        __syncthreads();
        sd[tid] += t;
        __syncthreads();
    }
    int excl = sd[tid] - sum;
    if (i0 < NJ) cnt[i0] = excl;
    if (i0 + 1 < NJ) cnt[i0 + 1] = excl + v0;
    if (tid == 511) g_tile[r * 128 + tile] = sd[511];
}

__global__ __launch_bounds__(128) void k_scan2(int ntiles) {
    __shared__ int sd[128];
    int r = blockIdx.x, tid = threadIdx.x;
    int v = (tid < ntiles) ? g_tile[r * 128 + tid] : 0;
    sd[tid] = v;
    __syncthreads();
    #pragma unroll
    for (int o = 1; o < 128; o <<= 1) {
        int t = (tid >= o) ? sd[tid - o] : 0;
        __syncthreads();
        sd[tid] += t;
        __syncthreads();
    }
    if (tid < ntiles) g_tile[r * 128 + tid] = sd[tid] - v;
}

__global__ __launch_bounds__(512) void k_scan3() {
    int r = blockIdx.y, tile = blockIdx.x, tid = threadIdx.x;
    int* cnt = g_off + r * (NJ + 1);
    int carry = g_tile[r * 128 + tile];
    int i0 = tile * 1024 + 2 * tid;
    #pragma unroll
    for (int l = 0; l < 2; l++) {
        int i = i0 + l;
        if (i < NJ) {
            int o = cnt[i] + carry;
            cnt[i] = o;
            g_cur[r * NJ + i] = o;
        }
    }
    if (tile == 0 && tid == 0) cnt[NJ] = EE;
}

__global__ void k_fill5(const int* __restrict__ s0, const int* __restrict__ d0,
                        const int* __restrict__ s1, const int* __restrict__ d1,
                        const int* __restrict__ s2, const int* __restrict__ d2,
                        const int* __restrict__ s3, const int* __restrict__ d3,
                        const int* __restrict__ s4, const int* __restrict__ d4) {
    for (int i = blockIdx.x * blockDim.x + threadIdx.x; i < EE; i += gridDim.x * blockDim.x) {
        int t;
        t = atomicAdd(&g_cur[0 * NJ + d0[i]], 1); g_esrc[0 * EE + t] = s0[i];
        t = atomicAdd(&g_cur[1 * NJ + d1[i]], 1); g_esrc[1 * EE + t] = s1[i];
        t = atomicAdd(&g_cur[2 * NJ + d2[i]], 1); g_esrc[2 * EE + t] = s2[i];
        t = atomicAdd(&g_cur[3 * NJ + d3[i]], 1); g_esrc[3 * EE + t] = s3[i];
        t = atomicAdd(&g_cur[4 * NJ + d4[i]], 1); g_esrc[4 * EE + t] = s4[i];
    }
}

// ---------------- alpha: per-node softmax over each relation's edges ----------------
__global__ void k_alpha() {
    int j = blockIdx.x * blockDim.x + threadIdx.x;
    if (j >= NJ) return;
    const float* drow = g_resad + (size_t)j * NCOMB + 256;
    #pragma unroll
    for (int r = 0; r < 5; r++) {
        int beg = g_off[r * (NJ + 1) + j];
        int end = g_off[r * (NJ + 1) + j + 1];
        if (beg == end) continue;
        float4 d4 = *(const float4*)(drow + r * 4);
        int hsb = c_hsb[r];
        const int* es = g_esrc + r * EE;
        float4* wv = g_walpha + (size_t)r * EE;
        float m0 = -1e30f, m1 = -1e30f, m2 = -1e30f, m3 = -1e30f;
        for (int t = beg; t < end; t++) {
            int s = es[t];
            float4 a = *(const float4*)(g_as + (size_t)(hsb + s) * 4);
            m0 = fmaxf(m0, lrelu(a.x + d4.x));
            m1 = fmaxf(m1, lrelu(a.y + d4.y));
            m2 = fmaxf(m2, lrelu(a.z + d4.z));
            m3 = fmaxf(m3, lrelu(a.w + d4.w));
        }
        float den0 = 0.f, den1 = 0.f, den2 = 0.f, den3 = 0.f;
        for (int t = beg; t < end; t++) {
            int s = es[t];
            float4 a = *(const float4*)(g_as + (size_t)(hsb + s) * 4);
            float4 w;
            w.x = __expf(lrelu(a.x + d4.x) - m0);
            w.y = __expf(lrelu(a.y + d4.y) - m1);
            w.z = __expf(lrelu(a.z + d4.z) - m2);
            w.w = __expf(lrelu(a.w + d4.w) - m3);
            den0 += w.x; den1 += w.y; den2 += w.z; den3 += w.w;
            wv[t] = w;
        }
        float i0 = 1.f / (den0 + 1e-16f), i1 = 1.f / (den1 + 1e-16f);
        float i2 = 1.f / (den2 + 1e-16f), i3 = 1.f / (den3 + 1e-16f);
        for (int t = beg; t < end; t++) {
            float4 w = wv[t];
            w.x *= i0; w.y *= i1; w.z *= i2; w.w *= i3;
            wv[t] = w;
        }
    }
}

// ---------------- fused gather + residual + ReLU + LayerNorm (sync-free gather) ----------------
__global__ __launch_bounds__(256) void k_main2(const float* __restrict__ gamma,
                                               const float* __restrict__ beta,
                                               float* __restrict__ out) {
    __shared__ float s_r1[8], s_r2[8];
    int j = blockIdx.x;
    int tid = threadIdx.x;
    int h = tid >> 6;
    float acc = g_resad[(size_t)j * NCOMB + tid] + g_bsum[tid];

    #pragma unroll
    for (int r = 0; r < 5; r++) {
        int beg = g_off[r * (NJ + 1) + j];
        int end = g_off[r * (NJ + 1) + j + 1];
        if (beg == end) continue;
        const int* es = g_esrc + r * EE;
        const float* wv = (const float*)g_walpha + (size_t)r * EE * 4;
        const float* hsr = g_hs + (size_t)c_hsb[r] * 256;
        int s = __ldg(es + beg);
        float w = __ldg(wv + (size_t)beg * 4 + h);
        float v = __ldg(hsr + (size_t)s * 256 + tid);
        for (int t = beg + 1; t < end; t++) {
            int s2 = __ldg(es + t);
            float w2 = __ldg(wv + (size_t)t * 4 + h);
            float v2 = __ldg(hsr + (size_t)s2 * 256 + tid);
            acc = fmaf(w, v, acc);
            w = w2; v = v2;
        }
        acc = fmaf(w, v, acc);
    }

    // ReLU + LayerNorm over 256 channels
    float v = fmaxf(acc, 0.f);
    float s1 = v, s2 = v * v;
    #pragma unroll
    for (int o = 16; o > 0; o >>= 1) {
        s1 += __shfl_xor_sync(0xffffffffu, s1, o);
        s2 += __shfl_xor_sync(0xffffffffu, s2, o);
    }
    int w = tid >> 5;
    if ((tid & 31) == 0) { s_r1[w] = s1; s_r2[w] = s2; }
    __syncthreads();
    if (tid < 32) {
        float a = (tid < 8) ? s_r1[tid] : 0.f;
        float b = (tid < 8) ? s_r2[tid] : 0.f;
        #pragma unroll
        for (int o = 4; o > 0; o >>= 1) {
            a += __shfl_xor_sync(0xffffffffu, a, o);
            b += __shfl_xor_sync(0xffffffffu, b, o);
        }
        if (tid == 0) { s_r1[0] = a; s_r2[0] = b; }
    }
    __syncthreads();
    float mu = s_r1[0] * (1.f / 256.f);
    float var = s_r2[0] * (1.f / 256.f) - mu * mu;
    out[(size_t)j * 256 + tid] = (v - mu) * rsqrtf(var + 1e-5f) * gamma[tid] + beta[tid];
}

// ---------------- launch ----------------
extern "C" void kernel_launch(void* const* d_in, const int* in_sizes, int n_in,
                              void* d_out, int out_size) {
    const float* x_job     = (const float*)d_in[0];
    const float* x_station = (const float*)d_in[1];
    const float* x_machine = (const float*)d_in[2];
    const float* x_robot   = (const float*)d_in[3];
    const int* srcp[5] = {(const int*)d_in[4], (const int*)d_in[6], (const int*)d_in[8],
                          (const int*)d_in[10], (const int*)d_in[12]};
    const int* dstp[5] = {(const int*)d_in[5], (const int*)d_in[7], (const int*)d_in[9],
                          (const int*)d_in[11], (const int*)d_in[13]};
    const float* Ws      = (const float*)d_in[14];
    const float* att_src = (const float*)d_in[15];
    const float* att_dst = (const float*)d_in[16];
    const float* biases  = (const float*)d_in[17];
    const float* W_res   = (const float*)d_in[18];
    const float* gamma   = (const float*)d_in[19];
    const float* beta    = (const float*)d_in[20];
    float* out = (float*)d_out;

    (void)in_sizes; (void)n_in; (void)out_size;

    const float* xs[5] = {x_station, x_station, x_machine, x_machine, x_robot};
    const int Ms[5]  = {NS, NS, NM, NM, NR};
    const int hb[5]  = {0, 20000, 40000, 50000, 60000};
    const int ntiles = (NJ + 1023) / 1024;   // 98

    // prep
    k_prep_w<<<DIN, NCOMB>>>(W_res, Ws, att_dst);
    k_bsum<<<1, 256>>>(biases);
    k_zero<<<256, 256>>>();

    // GEMMs: hs per relation
    for (int r = 0; r < 5; r++) {
        dim3 grid(256 / 64, (Ms[r] + 127) / 128);
        k_gemm<<<grid, 256>>>(xs[r], Ms[r], Ws + (size_t)r * DIN * 256, 256, 0, hb[r] * 256);
    }
    // combined residual + a_dst GEMM (B = g_wcomb selected device-side via mode==1)
    {
        dim3 grid(NCOMB / 64, (NJ + 127) / 128);
        k_gemm<<<grid, 256>>>(x_job, NJ, (const float*)nullptr, NCOMB, 1, 0);
    }
    // a_src reductions
    for (int r = 0; r < 5; r++) {
        int blocks = (Ms[r] + 7) / 8;
        k_as<<<blocks, 256>>>(att_src + r * 256, hb[r], Ms[r]);
    }
    // CSR build (parallel scan)
    k_hist5<<<512, 256>>>(dstp[0], dstp[1], dstp[2], dstp[3], dstp[4]);
    k_scan1<<<dim3(ntiles, 5), 512>>>();
    k_scan2<<<5, 128>>>(ntiles);
    k_scan3<<<dim3(ntiles, 5), 512>>>();
    k_fill5<<<512, 256>>>(srcp[0], dstp[0], srcp[1], dstp[1], srcp[2], dstp[2],
                          srcp[3], dstp[3], srcp[4], dstp[4]);

    // per-edge normalized attention
    k_alpha<<<(NJ + 255) / 256, 256>>>();

    // fused gather + residual + relu + layernorm
    k_main2<<<NJ, 256>>>(gamma, beta, out);
}

// round 4
// speedup vs baseline: 1.6071x; 1.2478x over previous
#include <cuda_runtime.h>
#include <cstdint>
#include <cstddef>

// Problem constants (fixed by the dataset)
#define NJ   100000
#define NS   20000
#define NM   10000
#define NR   5000
#define EE   250000
#define DIN  128
#define OUTD 256
#define NTOT 65000      // concatenated src rows: 20000+20000+10000+10000+5000
#define NCOMB 320       // W_res(256) + Wd(20) + pad(44)

typedef unsigned long long ull;

// ---------------- device scratch (static; no runtime allocation) ----------------
__device__ __align__(16) float g_hs[(size_t)NTOT * 256];   // per-relation hs = x_src @ W_r
__device__ __align__(16) float g_as[NTOT * 4];             // a_src per node per head
__device__ __align__(16) float g_resad[(size_t)NJ * NCOMB];// [0:256)=x_job@W_res, [256:276)=a_dst
__device__ float g_wcomb[DIN * NCOMB];                     // combined [W_res | Wd | 0]
__device__ float g_bsum[OUTD];                             // sum of relation biases
__device__ int   g_off[5 * (NJ + 1)];                      // CSR offsets per relation
__device__ int   g_cur[5 * NJ];                            // fill cursors
__device__ int   g_esrc[5 * EE];                           // CSR: src node per slot
__device__ float4 g_walpha[5 * EE];                        // normalized attention per edge (4 heads)
__device__ int   g_tile[5 * 128];                          // scan tile sums

__constant__ int c_hsb[5] = {0, 20000, 40000, 50000, 60000};

__device__ __forceinline__ float lrelu(float v) { return v > 0.f ? v : 0.2f * v; }

__device__ __forceinline__ void fma2(ull& d, ull a, ull b) {
    asm("fma.rn.f32x2 %0, %1, %2, %0;" : "+l"(d) : "l"(a), "l"(b));
}
__device__ __forceinline__ ull pack2(float v) {
    ull r;
    asm("mov.b64 %0, {%1, %1};" : "=l"(r) : "f"(v));
    return r;
}
__device__ __forceinline__ void unpk(float& lo, float& hi, ull v) {
    asm("mov.b64 {%0,%1}, %2;" : "=f"(lo), "=f"(hi) : "l"(v));
}

// ---------------- prep: build combined W matrix [W_res | Wd(r,h) | pad] ----------------
__global__ void k_prep_w(const float* __restrict__ W_res, const float* __restrict__ Ws,
                         const float* __restrict__ att_dst) {
    int k = blockIdx.x;           // 0..127
    int col = threadIdx.x;        // 0..319
    float v = 0.f;
    if (col < 256) {
        v = W_res[k * 256 + col];
    } else if (col < 276) {
        int rr = (col - 256) >> 2, hh = (col - 256) & 3;
        const float* w = Ws + ((size_t)rr * DIN + k) * 256 + hh * 64;
        const float* a = att_dst + rr * 256 + hh * 64;
        float s = 0.f;
        #pragma unroll
        for (int c = 0; c < 64; c++) s += w[c] * a[c];
        v = s;
    }
    g_wcomb[k * NCOMB + col] = v;
}

__global__ void k_bsum(const float* __restrict__ biases) {
    int t = threadIdx.x;
    float s = 0.f;
    #pragma unroll
    for (int r = 0; r < 5; r++) s += biases[r * 256 + t];
    g_bsum[t] = s;
}

__global__ void k_zero() {
    int n = 5 * (NJ + 1);
    for (int i = blockIdx.x * blockDim.x + threadIdx.x; i < n; i += gridDim.x * blockDim.x)
        g_off[i] = 0;
}

// ---------------- f32x2 SGEMM: C[M,N] = A[M,128] @ B[128,N]; BM=128 BN=128 BK=16 ----------------
// Thread tile 8x8 (two 4-col groups at tx*4 and 64+tx*4). B col-pairs are adjacent
// floats in smem (natural ull), A scalar packed (a,a) with 1 mov each.
// mode==0 -> B=Bin, C=g_hs+coff ; mode==1 -> B=g_wcomb, C=g_resad+coff (device-side!)
__global__ __launch_bounds__(256, 2) void k_gemm(const float* __restrict__ A, int M,
                                                 const float* __restrict__ Bin, int N,
                                                 int mode, int coff) {
    __shared__ float As[16][132];     // [k][m]
    __shared__ float Bs[16][128];     // [k][n]
    const float* __restrict__ B = (mode == 1) ? (const float*)g_wcomb : Bin;
    float* __restrict__ C = (mode == 1 ? g_resad : g_hs) + coff;
    int tid = threadIdx.x;
    int bm0 = blockIdx.y * 128, bn0 = blockIdx.x * 128;
    int tx = tid & 15, ty = tid >> 4;

    ull acc2[8][4];   // [row][col-pair]
    #pragma unroll
    for (int i = 0; i < 8; i++)
        #pragma unroll
        for (int j = 0; j < 4; j++) acc2[i][j] = 0ull;

    for (int k0 = 0; k0 < DIN; k0 += 16) {
        // A tile: 128 rows x 16 k (transposed into As[k][m])
        #pragma unroll
        for (int l = 0; l < 2; l++) {
            int f = tid + l * 256;
            int row = f >> 2, c4 = f & 3;
            int gr = bm0 + row;
            float4 av = make_float4(0.f, 0.f, 0.f, 0.f);
            if (gr < M) av = *(const float4*)(A + (size_t)gr * DIN + k0 + c4 * 4);
            As[c4 * 4 + 0][row] = av.x;
            As[c4 * 4 + 1][row] = av.y;
            As[c4 * 4 + 2][row] = av.z;
            As[c4 * 4 + 3][row] = av.w;
        }
        // B tile: 16 k-rows x 128 cols, conflict-free float4 (N-guarded)
        #pragma unroll
        for (int l = 0; l < 2; l++) {
            int row = (tid >> 5) + l * 8;
            int c = tid & 31;
            int col = bn0 + c * 4;
            float4 bv = make_float4(0.f, 0.f, 0.f, 0.f);
            if (col < N) bv = *(const float4*)(B + (size_t)(k0 + row) * N + col);
            *(float4*)&Bs[row][c * 4] = bv;
        }
        __syncthreads();
        #pragma unroll
        for (int kk = 0; kk < 16; kk++) {
            float4 a0 = *(const float4*)&As[kk][ty * 8];
            float4 a1 = *(const float4*)&As[kk][ty * 8 + 4];
            ulonglong2 bl = *(const ulonglong2*)&Bs[kk][tx * 4];        // cols tx*4..+3
            ulonglong2 bh = *(const ulonglong2*)&Bs[kk][64 + tx * 4];   // cols 64+tx*4..+3
            ull ap[8];
            ap[0] = pack2(a0.x); ap[1] = pack2(a0.y);
            ap[2] = pack2(a0.z); ap[3] = pack2(a0.w);
            ap[4] = pack2(a1.x); ap[5] = pack2(a1.y);
            ap[6] = pack2(a1.z); ap[7] = pack2(a1.w);
            #pragma unroll
            for (int i = 0; i < 8; i++) {
                fma2(acc2[i][0], ap[i], bl.x);
                fma2(acc2[i][1], ap[i], bl.y);
                fma2(acc2[i][2], ap[i], bh.x);
                fma2(acc2[i][3], ap[i], bh.y);
            }
        }
        __syncthreads();
    }
    #pragma unroll
    for (int i = 0; i < 8; i++) {
        int gr = bm0 + ty * 8 + i;
        if (gr >= M) continue;
        float l0, h0, l1, h1, l2, h2, l3, h3;
        unpk(l0, h0, acc2[i][0]); unpk(l1, h1, acc2[i][1]);
        unpk(l2, h2, acc2[i][2]); unpk(l3, h3, acc2[i][3]);
        int c0 = bn0 + tx * 4, c1 = bn0 + 64 + tx * 4;
        if (c0 < N) *(float4*)(C + (size_t)gr * N + c0) = make_float4(l0, h0, l1, h1);
        if (c1 < N) *(float4*)(C + (size_t)gr * N + c1) = make_float4(l2, h2, l3, h3);
    }
}

// ---------------- a_src reduction: one warp per node ----------------
__global__ void k_as(const float* __restrict__ att, int base, int M) {
    int node = blockIdx.x * 8 + (threadIdx.x >> 5);
    if (node >= M) return;
    int lane = threadIdx.x & 31;
    const float* hrow = g_hs + (size_t)(base + node) * 256 + lane * 8;
    const float* a = att + lane * 8;
    float4 h0 = *(const float4*)hrow;
    float4 h1 = *(const float4*)(hrow + 4);
    float4 a0 = *(const float4*)a;
    float4 a1 = *(const float4*)(a + 4);
    float p = h0.x * a0.x + h0.y * a0.y + h0.z * a0.z + h0.w * a0.w +
              h1.x * a1.x + h1.y * a1.y + h1.z * a1.z + h1.w * a1.w;
    p += __shfl_xor_sync(0xffffffffu, p, 4);
    p += __shfl_xor_sync(0xffffffffu, p, 2);
    p += __shfl_xor_sync(0xffffffffu, p, 1);
    if ((lane & 7) == 0) g_as[(size_t)(base + node) * 4 + (lane >> 3)] = p;
}

// ---------------- CSR build ----------------
__global__ void k_hist5(const int* __restrict__ d0, const int* __restrict__ d1,
                        const int* __restrict__ d2, const int* __restrict__ d3,
                        const int* __restrict__ d4) {
    for (int i = blockIdx.x * blockDim.x + threadIdx.x; i < EE; i += gridDim.x * blockDim.x) {
        atomicAdd(&g_off[0 * (NJ + 1) + d0[i]], 1);
        atomicAdd(&g_off[1 * (NJ + 1) + d1[i]], 1);
        atomicAdd(&g_off[2 * (NJ + 1) + d2[i]], 1);
        atomicAdd(&g_off[3 * (NJ + 1) + d3[i]], 1);
        atomicAdd(&g_off[4 * (NJ + 1) + d4[i]], 1);
    }
}

__global__ __launch_bounds__(512) void k_scan1() {
    __shared__ int sd[512];
    int r = blockIdx.y, tile = blockIdx.x, tid = threadIdx.x;
    int* cnt = g_off + r * (NJ + 1);
    int i0 = tile * 1024 + 2 * tid;
    int v0 = (i0 < NJ) ? cnt[i0] : 0;
    int v1 = (i0 + 1 < NJ) ? cnt[i0 + 1] : 0;
    int sum = v0 + v1;
    sd[tid] = sum;
    __syncthreads();
    #pragma unroll
    for (int o = 1; o < 512; o <<= 1) {
        int t = (tid >= o) ? sd[tid - o] : 0;
        __syncthreads();
        sd[tid] += t;
        __syncthreads();
    }
    int excl = sd[tid] - sum;
    if (i0 < NJ) cnt[i0] = excl;
    if (i0 + 1 < NJ) cnt[i0 + 1] = excl + v0;
    if (tid == 511) g_tile[r * 128 + tile] = sd[511];
}

__global__ __launch_bounds__(128) void k_scan2(int ntiles) {
    __shared__ int sd[128];
    int r = blockIdx.x, tid = threadIdx.x;
    int v = (tid < ntiles) ? g_tile[r * 128 + tid] : 0;
    sd[tid] = v;
    __syncthreads();
    #pragma unroll
    for (int o = 1; o < 128; o <<= 1) {
        int t = (tid >= o) ? sd[tid - o] : 0;
        __syncthreads();
        sd[tid] += t;
        __syncthreads();
    }
    if (tid < ntiles) g_tile[r * 128 + tid] = sd[tid] - v;
}

__global__ __launch_bounds__(512) void k_scan3() {
    int r = blockIdx.y, tile = blockIdx.x, tid = threadIdx.x;
    int* cnt = g_off + r * (NJ + 1);
    int carry = g_tile[r * 128 + tile];
    int i0 = tile * 1024 + 2 * tid;
    #pragma unroll
    for (int l = 0; l < 2; l++) {
        int i = i0 + l;
        if (i < NJ) {
            int o = cnt[i] + carry;
            cnt[i] = o;
            g_cur[r * NJ + i] = o;
        }
    }
    if (tile == 0 && tid == 0) cnt[NJ] = EE;
}

__global__ void k_fill5(const int* __restrict__ s0, const int* __restrict__ d0,
                        const int* __restrict__ s1, const int* __restrict__ d1,
                        const int* __restrict__ s2, const int* __restrict__ d2,
                        const int* __restrict__ s3, const int* __restrict__ d3,
                        const int* __restrict__ s4, const int* __restrict__ d4) {
    for (int i = blockIdx.x * blockDim.x + threadIdx.x; i < EE; i += gridDim.x * blockDim.x) {
        int t;
        t = atomicAdd(&g_cur[0 * NJ + d0[i]], 1); g_esrc[0 * EE + t] = s0[i];
        t = atomicAdd(&g_cur[1 * NJ + d1[i]], 1); g_esrc[1 * EE + t] = s1[i];
        t = atomicAdd(&g_cur[2 * NJ + d2[i]], 1); g_esrc[2 * EE + t] = s2[i];
        t = atomicAdd(&g_cur[3 * NJ + d3[i]], 1); g_esrc[3 * EE + t] = s3[i];
        t = atomicAdd(&g_cur[4 * NJ + d4[i]], 1); g_esrc[4 * EE + t] = s4[i];
    }
}

// ---------------- alpha: per-node softmax over each relation's edges ----------------
__global__ void k_alpha() {
    int j = blockIdx.x * blockDim.x + threadIdx.x;
    if (j >= NJ) return;
    const float* drow = g_resad + (size_t)j * NCOMB + 256;
    #pragma unroll
    for (int r = 0; r < 5; r++) {
        int beg = g_off[r * (NJ + 1) + j];
        int end = g_off[r * (NJ + 1) + j + 1];
        if (beg == end) continue;
        float4 d4 = *(const float4*)(drow + r * 4);
        int hsb = c_hsb[r];
        const int* es = g_esrc + r * EE;
        float4* wv = g_walpha + (size_t)r * EE;
        float m0 = -1e30f, m1 = -1e30f, m2 = -1e30f, m3 = -1e30f;
        for (int t = beg; t < end; t++) {
            int s = es[t];
            float4 a = *(const float4*)(g_as + (size_t)(hsb + s) * 4);
            m0 = fmaxf(m0, lrelu(a.x + d4.x));
            m1 = fmaxf(m1, lrelu(a.y + d4.y));
            m2 = fmaxf(m2, lrelu(a.z + d4.z));
            m3 = fmaxf(m3, lrelu(a.w + d4.w));
        }
        float den0 = 0.f, den1 = 0.f, den2 = 0.f, den3 = 0.f;
        for (int t = beg; t < end; t++) {
            int s = es[t];
            float4 a = *(const float4*)(g_as + (size_t)(hsb + s) * 4);
            float4 w;
            w.x = __expf(lrelu(a.x + d4.x) - m0);
            w.y = __expf(lrelu(a.y + d4.y) - m1);
            w.z = __expf(lrelu(a.z + d4.z) - m2);
            w.w = __expf(lrelu(a.w + d4.w) - m3);
            den0 += w.x; den1 += w.y; den2 += w.z; den3 += w.w;
            wv[t] = w;
        }
        float i0 = 1.f / (den0 + 1e-16f), i1 = 1.f / (den1 + 1e-16f);
        float i2 = 1.f / (den2 + 1e-16f), i3 = 1.f / (den3 + 1e-16f);
        for (int t = beg; t < end; t++) {
            float4 w = wv[t];
            w.x *= i0; w.y *= i1; w.z *= i2; w.w *= i3;
            wv[t] = w;
        }
    }
}

// ---------------- fused gather + residual + ReLU + LayerNorm (sync-free gather) ----------------
__global__ __launch_bounds__(256) void k_main2(const float* __restrict__ gamma,
                                               const float* __restrict__ beta,
                                               float* __restrict__ out) {
    __shared__ float s_r1[8], s_r2[8];
    int j = blockIdx.x;
    int tid = threadIdx.x;
    int h = tid >> 6;
    float acc = g_resad[(size_t)j * NCOMB + tid] + g_bsum[tid];

    #pragma unroll
    for (int r = 0; r < 5; r++) {
        int beg = g_off[r * (NJ + 1) + j];
        int end = g_off[r * (NJ + 1) + j + 1];
        if (beg == end) continue;
        const int* es = g_esrc + r * EE;
        const float* wv = (const float*)g_walpha + (size_t)r * EE * 4;
        const float* hsr = g_hs + (size_t)c_hsb[r] * 256;
        int s = __ldg(es + beg);
        float w = __ldg(wv + (size_t)beg * 4 + h);
        float v = __ldg(hsr + (size_t)s * 256 + tid);
        for (int t = beg + 1; t < end; t++) {
            int s2 = __ldg(es + t);
            float w2 = __ldg(wv + (size_t)t * 4 + h);
            float v2 = __ldg(hsr + (size_t)s2 * 256 + tid);
            acc = fmaf(w, v, acc);
            w = w2; v = v2;
        }
        acc = fmaf(w, v, acc);
    }

    // ReLU + LayerNorm over 256 channels
    float v = fmaxf(acc, 0.f);
    float s1 = v, s2 = v * v;
    #pragma unroll
    for (int o = 16; o > 0; o >>= 1) {
        s1 += __shfl_xor_sync(0xffffffffu, s1, o);
        s2 += __shfl_xor_sync(0xffffffffu, s2, o);
    }
    int w = tid >> 5;
    if ((tid & 31) == 0) { s_r1[w] = s1; s_r2[w] = s2; }
    __syncthreads();
    if (tid < 32) {
        float a = (tid < 8) ? s_r1[tid] : 0.f;
        float b = (tid < 8) ? s_r2[tid] : 0.f;
        #pragma unroll
        for (int o = 4; o > 0; o >>= 1) {
            a += __shfl_xor_sync(0xffffffffu, a, o);
            b += __shfl_xor_sync(0xffffffffu, b, o);
        }
        if (tid == 0) { s_r1[0] = a; s_r2[0] = b; }
    }
    __syncthreads();
    float mu = s_r1[0] * (1.f / 256.f);
    float var = s_r2[0] * (1.f / 256.f) - mu * mu;
    out[(size_t)j * 256 + tid] = (v - mu) * rsqrtf(var + 1e-5f) * gamma[tid] + beta[tid];
}

// ---------------- launch ----------------
extern "C" void kernel_launch(void* const* d_in, const int* in_sizes, int n_in,
                              void* d_out, int out_size) {
    const float* x_job     = (const float*)d_in[0];
    const float* x_station = (const float*)d_in[1];
    const float* x_machine = (const float*)d_in[2];
    const float* x_robot   = (const float*)d_in[3];
    const int* srcp[5] = {(const int*)d_in[4], (const int*)d_in[6], (const int*)d_in[8],
                          (const int*)d_in[10], (const int*)d_in[12]};
    const int* dstp[5] = {(const int*)d_in[5], (const int*)d_in[7], (const int*)d_in[9],
                          (const int*)d_in[11], (const int*)d_in[13]};
    const float* Ws      = (const float*)d_in[14];
    const float* att_src = (const float*)d_in[15];
    const float* att_dst = (const float*)d_in[16];
    const float* biases  = (const float*)d_in[17];
    const float* W_res   = (const float*)d_in[18];
    const float* gamma   = (const float*)d_in[19];
    const float* beta    = (const float*)d_in[20];
    float* out = (float*)d_out;

    (void)in_sizes; (void)n_in; (void)out_size;

    const float* xs[5] = {x_station, x_station, x_machine, x_machine, x_robot};
    const int Ms[5]  = {NS, NS, NM, NM, NR};
    const int hb[5]  = {0, 20000, 40000, 50000, 60000};
    const int ntiles = (NJ + 1023) / 1024;   // 98

    // prep
    k_prep_w<<<DIN, NCOMB>>>(W_res, Ws, att_dst);
    k_bsum<<<1, 256>>>(biases);
    k_zero<<<256, 256>>>();

    // GEMMs: hs per relation (N=256 -> 2 col-tiles)
    for (int r = 0; r < 5; r++) {
        dim3 grid(2, (Ms[r] + 127) / 128);
        k_gemm<<<grid, 256>>>(xs[r], Ms[r], Ws + (size_t)r * DIN * 256, 256, 0, hb[r] * 256);
    }
    // combined residual + a_dst GEMM (B = g_wcomb selected device-side; N=320 -> 3 col-tiles)
    {
        dim3 grid(3, (NJ + 127) / 128);
        k_gemm<<<grid, 256>>>(x_job, NJ, (const float*)nullptr, NCOMB, 1, 0);
    }
    // a_src reductions
    for (int r = 0; r < 5; r++) {
        int blocks = (Ms[r] + 7) / 8;
        k_as<<<blocks, 256>>>(att_src + r * 256, hb[r], Ms[r]);
    }
    // CSR build (parallel scan)
    k_hist5<<<512, 256>>>(dstp[0], dstp[1], dstp[2], dstp[3], dstp[4]);
    k_scan1<<<dim3(ntiles, 5), 512>>>();
    k_scan2<<<5, 128>>>(ntiles);
    k_scan3<<<dim3(ntiles, 5), 512>>>();
    k_fill5<<<512, 256>>>(srcp[0], dstp[0], srcp[1], dstp[1], srcp[2], dstp[2],
                          srcp[3], dstp[3], srcp[4], dstp[4]);

    // per-edge normalized attention
    k_alpha<<<(NJ + 255) / 256, 256>>>();

    // fused gather + residual + relu + layernorm
    k_main2<<<NJ, 256>>>(gamma, beta, out);
}

// round 6
// speedup vs baseline: 1.7653x; 1.0985x over previous
#include <cuda_runtime.h>
#include <cuda_bf16.h>
#include <cstdint>
#include <cstddef>

// Problem constants
#define NJ   100000
#define NS   20000
#define NM   10000
#define NR   5000
#define EE   250000
#define DIN  128
#define OUTD 256
#define NTOT 65000

typedef unsigned long long ull;

// ---------------- device scratch ----------------
__device__ __align__(16) __nv_bfloat16 g_Bh[6 * 32768];  // [b][n(256)][k(128)] swizzled, hi
__device__ __align__(16) __nv_bfloat16 g_Bl[6 * 32768];  // lo
__device__ __align__(16) float g_hs[(size_t)NTOT * 256];
__device__ __align__(16) float g_res[(size_t)NJ * 256];
__device__ __align__(16) float g_as[NTOT * 4];
__device__ __align__(16) float g_ad[(size_t)NJ * 20];
__device__ float g_wd[20 * 128];
__device__ float g_bsum[OUTD];
__device__ int   g_off[5 * (NJ + 1)];
__device__ int   g_cur[5 * NJ];
__device__ int   g_esrc[5 * EE];
__device__ float4 g_walpha[5 * EE];
__device__ int   g_tile[5 * 128];

__constant__ int c_hsb[5] = {0, 20000, 40000, 50000, 60000};

__device__ __forceinline__ float lrelu(float v) { return v > 0.f ? v : 0.2f * v; }

__device__ __forceinline__ uint32_t smem_u32(const void* p) {
    uint32_t a;
    asm("{ .reg .u64 t; cvta.to.shared.u64 t, %1; cvt.u32.u64 %0, t; }" : "=r"(a) : "l"(p));
    return a;
}
__device__ __forceinline__ void ldmat4(uint32_t& r0, uint32_t& r1, uint32_t& r2, uint32_t& r3,
                                       uint32_t addr) {
    asm volatile("ldmatrix.sync.aligned.m8n8.x4.shared.b16 {%0,%1,%2,%3}, [%4];"
                 : "=r"(r0), "=r"(r1), "=r"(r2), "=r"(r3) : "r"(addr));
}
__device__ __forceinline__ void mma16816(float* c, uint32_t a0, uint32_t a1, uint32_t a2,
                                         uint32_t a3, uint32_t b0, uint32_t b1) {
    asm volatile(
        "mma.sync.aligned.m16n8k16.row.col.f32.bf16.bf16.f32 "
        "{%0,%1,%2,%3}, {%4,%5,%6,%7}, {%8,%9}, {%0,%1,%2,%3};"
        : "+f"(c[0]), "+f"(c[1]), "+f"(c[2]), "+f"(c[3])
        : "r"(a0), "r"(a1), "r"(a2), "r"(a3), "r"(b0), "r"(b1));
}
__device__ __forceinline__ uint32_t pkbf(float a, float b) {
    __nv_bfloat162 t = __floats2bfloat162_rn(a, b);
    return *(uint32_t*)&t;
}

// smem layout (bytes): Ahi[0,32768) Alo[32768,65536) Bhi[65536,81920) Blo[81920,98304)
#define SM_ALO 32768
#define SM_BHI 65536
#define SM_BLO 81920
#define SMEM_SZ 98304

// ---------------- B convert/transpose into swizzled global images ----------------
// dst[b][n][k]: idx = b*32768 + n*128 + ((k>>3)^(n&7))*8 + (k&7)
__global__ void k_cvtB(const float* __restrict__ Ws, const float* __restrict__ W_res) {
    int n_tot = 6 * 32768;
    for (int i = blockIdx.x * blockDim.x + threadIdx.x; i < n_tot; i += gridDim.x * blockDim.x) {
        int b = i >> 15;
        int rem = i & 32767;
        int nn = rem >> 7, k = rem & 127;
        float v = (b < 5) ? Ws[((size_t)b * 128 + k) * 256 + nn] : W_res[(size_t)k * 256 + nn];
        __nv_bfloat16 h = __float2bfloat16(v);
        float lo = v - __bfloat162float(h);
        size_t idx = (size_t)b * 32768 + nn * 128 + (((k >> 3) ^ (nn & 7)) << 3) + (k & 7);
        g_Bh[idx] = h;
        g_Bl[idx] = __float2bfloat16(lo);
    }
}

// ---------------- HMMA bf16 3-pass GEMM: C[128m x 64n] per CTA ----------------
__global__ __launch_bounds__(256, 2) void k_mma(const float* __restrict__ A, int M,
                                                int bsel, int csel, int crow0) {
    extern __shared__ char smem[];
    uint32_t sb = smem_u32(smem);
    int tid = threadIdx.x;
    int wid = tid >> 5, lane = tid & 31;
    int n0 = blockIdx.x * 64;          // n tile (of 256)
    int m0 = blockIdx.y * 128;         // m tile

    // ---- A load + split-convert into swizzled smem (128 rows x 16 chunks of 8 bf16) ----
    {
        const float* Ag = A + (size_t)m0 * DIN;
        #pragma unroll
        for (int it = 0; it < 8; it++) {
            int id = tid + it * 256;           // 0..2047
            int r = id >> 4, c = id & 15;
            float4 v0 = make_float4(0.f, 0.f, 0.f, 0.f), v1 = v0;
            if (m0 + r < M) {
                v0 = *(const float4*)(Ag + (size_t)r * DIN + c * 8);
                v1 = *(const float4*)(Ag + (size_t)r * DIN + c * 8 + 4);
            }
            float f[8] = {v0.x, v0.y, v0.z, v0.w, v1.x, v1.y, v1.z, v1.w};
            float l[8];
            uint32_t hi[4], lo[4];
            #pragma unroll
            for (int q = 0; q < 8; q++) {
                __nv_bfloat16 h = __float2bfloat16(f[q]);
                l[q] = f[q] - __bfloat162float(h);
            }
            #pragma unroll
            for (int q = 0; q < 4; q++) {
                hi[q] = pkbf(f[2 * q], f[2 * q + 1]);
                lo[q] = pkbf(l[2 * q], l[2 * q + 1]);
            }
            uint32_t off = r * 256 + (((c ^ (r & 7))) << 4);
            *(uint4*)(smem + off) = make_uint4(hi[0], hi[1], hi[2], hi[3]);
            *(uint4*)(smem + SM_ALO + off) = make_uint4(lo[0], lo[1], lo[2], lo[3]);
        }
    }
    // ---- B copy (pre-swizzled rows n0..n0+63, linear) ----
    {
        const float4* sh = (const float4*)(g_Bh + (size_t)bsel * 32768 + n0 * 128);
        const float4* sl = (const float4*)(g_Bl + (size_t)bsel * 32768 + n0 * 128);
        float4* dh = (float4*)(smem + SM_BHI);
        float4* dl = (float4*)(smem + SM_BLO);
        #pragma unroll
        for (int l = 0; l < 4; l++) { int i = tid + l * 256; dh[i] = sh[i]; }
        #pragma unroll
        for (int l = 0; l < 4; l++) { int i = tid + l * 256; dl[i] = sl[i]; }
    }
    __syncthreads();

    // ---- warp tile 64m x 16n ----
    int m0w = (wid & 1) * 64;
    int n0w = (wid >> 1) * 16;
    float cf[4][2][4];
    #pragma unroll
    for (int i = 0; i < 4; i++)
        #pragma unroll
        for (int j = 0; j < 2; j++)
            #pragma unroll
            for (int q = 0; q < 4; q++) cf[i][j][q] = 0.f;

    int lr = lane & 7;
    #pragma unroll
    for (int pass = 0; pass < 3; pass++) {
        uint32_t aB = sb + ((pass == 2) ? SM_ALO : 0);
        uint32_t bB = sb + ((pass == 1) ? SM_BLO : SM_BHI);
        #pragma unroll
        for (int ks = 0; ks < 8; ks++) {
            // B frag: rows n0w + lr + (lane>>4)*8, chunk ks*2 + ((lane>>3)&1)
            uint32_t brow = n0w + lr + ((lane >> 4) << 3);
            uint32_t bch = (uint32_t)(ks * 2) + ((lane >> 3) & 1);
            uint32_t baddr = bB + brow * 256 + ((bch ^ (brow & 7)) << 4);
            uint32_t b0, b1, b2, b3;
            ldmat4(b0, b1, b2, b3, baddr);
            #pragma unroll
            for (int mt = 0; mt < 4; mt++) {
                uint32_t arow = m0w + mt * 16 + lr + (((lane >> 3) & 1) << 3);
                uint32_t ach = (uint32_t)(ks * 2) + (lane >> 4);
                uint32_t aaddr = aB + arow * 256 + ((ach ^ (arow & 7)) << 4);
                uint32_t a0, a1, a2, a3;
                ldmat4(a0, a1, a2, a3, aaddr);
                mma16816(cf[mt][0], a0, a1, a2, a3, b0, b1);
                mma16816(cf[mt][1], a0, a1, a2, a3, b2, b3);
            }
        }
    }

    // ---- epilogue ----
    {
        float* C = (csel ? g_res : g_hs);
        int mbase = m0 + m0w + (lane >> 2);
        int nbase = n0 + n0w + (lane & 3) * 2;
        #pragma unroll
        for (int mt = 0; mt < 4; mt++) {
            int m = mbase + mt * 16;
            #pragma unroll
            for (int nf = 0; nf < 2; nf++) {
                int n = nbase + nf * 8;
                if (m < M)
                    *(float2*)(C + (size_t)(crow0 + m) * 256 + n) =
                        make_float2(cf[mt][nf][0], cf[mt][nf][1]);
                if (m + 8 < M)
                    *(float2*)(C + (size_t)(crow0 + m + 8) * 256 + n) =
                        make_float2(cf[mt][nf][2], cf[mt][nf][3]);
            }
        }
    }
}

// ---------------- small prep kernels ----------------
__global__ void k_bsum(const float* __restrict__ biases) {
    int t = threadIdx.x;
    float s = 0.f;
    #pragma unroll
    for (int r = 0; r < 5; r++) s += biases[r * 256 + t];
    g_bsum[t] = s;
}

__global__ void k_zero() {
    int n = 5 * (NJ + 1);
    for (int i = blockIdx.x * blockDim.x + threadIdx.x; i < n; i += gridDim.x * blockDim.x)
        g_off[i] = 0;
}

// fold Wd[r,h][k] = sum_c Ws[r,k,h*64+c] * att_dst[r,h,c]
__global__ void k_wdf(const float* __restrict__ Ws, const float* __restrict__ att_dst) {
    int o = blockIdx.x;        // 0..19 = r*4+h
    int r = o >> 2, h = o & 3;
    int k = threadIdx.x;
    float s = 0.f;
    #pragma unroll
    for (int c = 0; c < 64; c++)
        s += Ws[((size_t)r * 128 + k) * 256 + h * 64 + c] * att_dst[r * 256 + h * 64 + c];
    g_wd[o * 128 + k] = s;
}

// a_dst in fp32: g_ad[j][20] = x_job[j] . wd[o]
__global__ __launch_bounds__(256) void k_ad(const float* __restrict__ xj) {
    __shared__ float swd[20][128];
    int tid = threadIdx.x;
    for (int i = tid; i < 2560; i += 256) swd[i >> 7][i & 127] = g_wd[i];
    __syncthreads();
    int j = blockIdx.x * 8 + (tid >> 5);
    if (j >= NJ) return;
    int lane = tid & 31;
    float4 x = *(const float4*)(xj + (size_t)j * 128 + lane * 4);
    #pragma unroll
    for (int o = 0; o < 20; o++) {
        const float* w = &swd[o][lane * 4];
        float p = x.x * w[0] + x.y * w[1] + x.z * w[2] + x.w * w[3];
        p += __shfl_xor_sync(0xffffffffu, p, 16);
        p += __shfl_xor_sync(0xffffffffu, p, 8);
        p += __shfl_xor_sync(0xffffffffu, p, 4);
        p += __shfl_xor_sync(0xffffffffu, p, 2);
        p += __shfl_xor_sync(0xffffffffu, p, 1);
        if (lane == 0) g_ad[(size_t)j * 20 + o] = p;
    }
}

// a_src: one warp per node, reads g_hs
__global__ void k_as(const float* __restrict__ att, int base, int M) {
    int node = blockIdx.x * 8 + (threadIdx.x >> 5);
    if (node >= M) return;
    int lane = threadIdx.x & 31;
    const float* hrow = g_hs + (size_t)(base + node) * 256 + lane * 8;
    const float* a = att + lane * 8;
    float4 h0 = *(const float4*)hrow;
    float4 h1 = *(const float4*)(hrow + 4);
    float4 a0 = *(const float4*)a;
    float4 a1 = *(const float4*)(a + 4);
    float p = h0.x * a0.x + h0.y * a0.y + h0.z * a0.z + h0.w * a0.w +
              h1.x * a1.x + h1.y * a1.y + h1.z * a1.z + h1.w * a1.w;
    p += __shfl_xor_sync(0xffffffffu, p, 4);
    p += __shfl_xor_sync(0xffffffffu, p, 2);
    p += __shfl_xor_sync(0xffffffffu, p, 1);
    if ((lane & 7) == 0) g_as[(size_t)(base + node) * 4 + (lane >> 3)] = p;
}

// ---------------- CSR build ----------------
__global__ void k_hist5(const int* __restrict__ d0, const int* __restrict__ d1,
                        const int* __restrict__ d2, const int* __restrict__ d3,
                        const int* __restrict__ d4) {
    for (int i = blockIdx.x * blockDim.x + threadIdx.x; i < EE; i += gridDim.x * blockDim.x) {
        atomicAdd(&g_off[0 * (NJ + 1) + d0[i]], 1);
        atomicAdd(&g_off[1 * (NJ + 1) + d1[i]], 1);
        atomicAdd(&g_off[2 * (NJ + 1) + d2[i]], 1);
        atomicAdd(&g_off[3 * (NJ + 1) + d3[i]], 1);
        atomicAdd(&g_off[4 * (NJ + 1) + d4[i]], 1);
    }
}

__global__ __launch_bounds__(512) void k_scan1() {
    __shared__ int sd[512];
    int r = blockIdx.y, tile = blockIdx.x, tid = threadIdx.x;
    int* cnt = g_off + r * (NJ + 1);
    int i0 = tile * 1024 + 2 * tid;
    int v0 = (i0 < NJ) ? cnt[i0] : 0;
    int v1 = (i0 + 1 < NJ) ? cnt[i0 + 1] : 0;
    int sum = v0 + v1;
    sd[tid] = sum;
    __syncthreads();
    #pragma unroll
    for (int o = 1; o < 512; o <<= 1) {
        int t = (tid >= o) ? sd[tid - o] : 0;
        __syncthreads();
        sd[tid] += t;
        __syncthreads();
    }
    int excl = sd[tid] - sum;
    if (i0 < NJ) cnt[i0] = excl;
    if (i0 + 1 < NJ) cnt[i0 + 1] = excl + v0;
    if (tid == 511) g_tile[r * 128 + tile] = sd[511];
}

__global__ __launch_bounds__(128) void k_scan2(int ntiles) {
    __shared__ int sd[128];
    int r = blockIdx.x, tid = threadIdx.x;
    int v = (tid < ntiles) ? g_tile[r * 128 + tid] : 0;
    sd[tid] = v;
    __syncthreads();
    #pragma unroll
    for (int o = 1; o < 128; o <<= 1) {
        int t = (tid >= o) ? sd[tid - o] : 0;
        __syncthreads();
        sd[tid] += t;
        __syncthreads();
    }
    if (tid < ntiles) g_tile[r * 128 + tid] = sd[tid] - v;
}

__global__ __launch_bounds__(512) void k_scan3() {
    int r = blockIdx.y, tile = blockIdx.x, tid = threadIdx.x;
    int* cnt = g_off + r * (NJ + 1);
    int carry = g_tile[r * 128 + tile];
    int i0 = tile * 1024 + 2 * tid;
    #pragma unroll
    for (int l = 0; l < 2; l++) {
        int i = i0 + l;
        if (i < NJ) {
            int o = cnt[i] + carry;
            cnt[i] = o;
            g_cur[r * NJ + i] = o;
        }
    }
    if (tile == 0 && tid == 0) cnt[NJ] = EE;
}

__global__ void k_fill5(const int* __restrict__ s0, const int* __restrict__ d0,
                        const int* __restrict__ s1, const int* __restrict__ d1,
                        const int* __restrict__ s2, const int* __restrict__ d2,
                        const int* __restrict__ s3, const int* __restrict__ d3,
                        const int* __restrict__ s4, const int* __restrict__ d4) {
    for (int i = blockIdx.x * blockDim.x + threadIdx.x; i < EE; i += gridDim.x * blockDim.x) {
        int t;
        t = atomicAdd(&g_cur[0 * NJ + d0[i]], 1); g_esrc[0 * EE + t] = s0[i];
        t = atomicAdd(&g_cur[1 * NJ + d1[i]], 1); g_esrc[1 * EE + t] = s1[i];
        t = atomicAdd(&g_cur[2 * NJ + d2[i]], 1); g_esrc[2 * EE + t] = s2[i];
        t = atomicAdd(&g_cur[3 * NJ + d3[i]], 1); g_esrc[3 * EE + t] = s3[i];
        t = atomicAdd(&g_cur[4 * NJ + d4[i]], 1); g_esrc[4 * EE + t] = s4[i];
    }
}

// ---------------- alpha ----------------
__global__ void k_alpha() {
    int j = blockIdx.x * blockDim.x + threadIdx.x;
    if (j >= NJ) return;
    #pragma unroll
    for (int r = 0; r < 5; r++) {
        int beg = g_off[r * (NJ + 1) + j];
        int end = g_off[r * (NJ + 1) + j + 1];
        if (beg == end) continue;
        float4 d4 = *(const float4*)(g_ad + (size_t)j * 20 + r * 4);
        int hsb = c_hsb[r];
        const int* es = g_esrc + r * EE;
        float4* wv = g_walpha + (size_t)r * EE;
        float m0 = -1e30f, m1 = -1e30f, m2 = -1e30f, m3 = -1e30f;
        for (int t = beg; t < end; t++) {
            int s = es[t];
            float4 a = *(const float4*)(g_as + (size_t)(hsb + s) * 4);
            m0 = fmaxf(m0, lrelu(a.x + d4.x));
            m1 = fmaxf(m1, lrelu(a.y + d4.y));
            m2 = fmaxf(m2, lrelu(a.z + d4.z));
            m3 = fmaxf(m3, lrelu(a.w + d4.w));
        }
        float den0 = 0.f, den1 = 0.f, den2 = 0.f, den3 = 0.f;
        for (int t = beg; t < end; t++) {
            int s = es[t];
            float4 a = *(const float4*)(g_as + (size_t)(hsb + s) * 4);
            float4 w;
            w.x = __expf(lrelu(a.x + d4.x) - m0);
            w.y = __expf(lrelu(a.y + d4.y) - m1);
            w.z = __expf(lrelu(a.z + d4.z) - m2);
            w.w = __expf(lrelu(a.w + d4.w) - m3);
            den0 += w.x; den1 += w.y; den2 += w.z; den3 += w.w;
            wv[t] = w;
        }
        float i0 = 1.f / (den0 + 1e-16f), i1 = 1.f / (den1 + 1e-16f);
        float i2 = 1.f / (den2 + 1e-16f), i3 = 1.f / (den3 + 1e-16f);
        for (int t = beg; t < end; t++) {
            float4 w = wv[t];
            w.x *= i0; w.y *= i1; w.z *= i2; w.w *= i3;
            wv[t] = w;
        }
    }
}

// ---------------- fused gather + residual + ReLU + LayerNorm ----------------
__global__ __launch_bounds__(256) void k_main2(const float* __restrict__ gamma,
                                               const float* __restrict__ beta,
                                               float* __restrict__ out) {
    __shared__ float s_r1[8], s_r2[8];
    int j = blockIdx.x;
    int tid = threadIdx.x;
    int h = tid >> 6;
    float acc = g_res[(size_t)j * 256 + tid] + g_bsum[tid];

    #pragma unroll
    for (int r = 0; r < 5; r++) {
        int beg = g_off[r * (NJ + 1) + j];
        int end = g_off[r * (NJ + 1) + j + 1];
        if (beg == end) continue;
        const int* es = g_esrc + r * EE;
        const float* wv = (const float*)g_walpha + (size_t)r * EE * 4;
        const float* hsr = g_hs + (size_t)c_hsb[r] * 256;
        int s = __ldg(es + beg);
        float w = __ldg(wv + (size_t)beg * 4 + h);
        float v = __ldg(hsr + (size_t)s * 256 + tid);
        for (int t = beg + 1; t < end; t++) {
            int s2 = __ldg(es + t);
            float w2 = __ldg(wv + (size_t)t * 4 + h);
            float v2 = __ldg(hsr + (size_t)s2 * 256 + tid);
            acc = fmaf(w, v, acc);
            w = w2; v = v2;
        }
        acc = fmaf(w, v, acc);
    }

    float v = fmaxf(acc, 0.f);
    float s1 = v, s2 = v * v;
    #pragma unroll
    for (int o = 16; o > 0; o >>= 1) {
        s1 += __shfl_xor_sync(0xffffffffu, s1, o);
        s2 += __shfl_xor_sync(0xffffffffu, s2, o);
    }
    int w = tid >> 5;
    if ((tid & 31) == 0) { s_r1[w] = s1; s_r2[w] = s2; }
    __syncthreads();
    if (tid < 32) {
        float a = (tid < 8) ? s_r1[tid] : 0.f;
        float b = (tid < 8) ? s_r2[tid] : 0.f;
        #pragma unroll
        for (int o = 4; o > 0; o >>= 1) {
            a += __shfl_xor_sync(0xffffffffu, a, o);
            b += __shfl_xor_sync(0xffffffffu, b, o);
        }
        if (tid == 0) { s_r1[0] = a; s_r2[0] = b; }
    }
    __syncthreads();
    float mu = s_r1[0] * (1.f / 256.f);
    float var = s_r2[0] * (1.f / 256.f) - mu * mu;
    out[(size_t)j * 256 + tid] = (v - mu) * rsqrtf(var + 1e-5f) * gamma[tid] + beta[tid];
}

// ---------------- launch ----------------
extern "C" void kernel_launch(void* const* d_in, const int* in_sizes, int n_in,
                              void* d_out, int out_size) {
    const float* x_job     = (const float*)d_in[0];
    const float* x_station = (const float*)d_in[1];
    const float* x_machine = (const float*)d_in[2];
    const float* x_robot   = (const float*)d_in[3];
    const int* srcp[5] = {(const int*)d_in[4], (const int*)d_in[6], (const int*)d_in[8],
                          (const int*)d_in[10], (const int*)d_in[12]};
    const int* dstp[5] = {(const int*)d_in[5], (const int*)d_in[7], (const int*)d_in[9],
                          (const int*)d_in[11], (const int*)d_in[13]};
    const float* Ws      = (const float*)d_in[14];
    const float* att_src = (const float*)d_in[15];
    const float* att_dst = (const float*)d_in[16];
    const float* biases  = (const float*)d_in[17];
    const float* W_res   = (const float*)d_in[18];
    const float* gamma   = (const float*)d_in[19];
    const float* beta    = (const float*)d_in[20];
    float* out = (float*)d_out;

    (void)in_sizes; (void)n_in; (void)out_size;

    cudaFuncSetAttribute(k_mma, cudaFuncAttributeMaxDynamicSharedMemorySize, SMEM_SZ);

    const float* xs[5] = {x_station, x_station, x_machine, x_machine, x_robot};
    const int Ms[5]    = {NS, NS, NM, NM, NR};
    const int hb[5]    = {0, 20000, 40000, 50000, 60000};
    const int ntiles = (NJ + 1023) / 1024;   // 98

    // prep
    k_bsum<<<1, 256>>>(biases);
    k_zero<<<256, 256>>>();
    k_wdf<<<20, 128>>>(Ws, att_dst);
    k_cvtB<<<192, 256>>>(Ws, W_res);

    // HMMA GEMMs: hs per relation
    for (int r = 0; r < 5; r++) {
        dim3 grid(4, (Ms[r] + 127) / 128);
        k_mma<<<grid, 256, SMEM_SZ>>>(xs[r], Ms[r], r, 0, hb[r]);
    }
    // residual GEMM: g_res = x_job @ W_res
    {
        dim3 grid(4, (NJ + 127) / 128);
        k_mma<<<grid, 256, SMEM_SZ>>>(x_job, NJ, 5, 1, 0);
    }

    // a_dst (fp32) and a_src
    k_ad<<<(NJ + 7) / 8, 256>>>(x_job);
    for (int r = 0; r < 5; r++) {
        int blocks = (Ms[r] + 7) / 8;
        k_as<<<blocks, 256>>>(att_src + r * 256, hb[r], Ms[r]);
    }

    // CSR build
    k_hist5<<<512, 256>>>(dstp[0], dstp[1], dstp[2], dstp[3], dstp[4]);
    k_scan1<<<dim3(ntiles, 5), 512>>>();
    k_scan2<<<5, 128>>>(ntiles);
    k_scan3<<<dim3(ntiles, 5), 512>>>();
    k_fill5<<<512, 256>>>(srcp[0], dstp[0], srcp[1], dstp[1], srcp[2], dstp[2],
                          srcp[3], dstp[3], srcp[4], dstp[4]);

    // attention + fused output
    k_alpha<<<(NJ + 255) / 256, 256>>>();
    k_main2<<<NJ, 256>>>(gamma, beta, out);
}